// round 1
// baseline (speedup 1.0000x reference)
#include <cuda_runtime.h>
#include <cuda_bf16.h>

// SMorph layer: y = softdilate(x,k1) + softerode(x,k2) + bias
// Factorized:  exp(p+k) = exp(p)*exp(k) turns both soft-morph ops into
// four 3x3 convolutions over per-pixel maps {e, x*e, em, -x*em} with
// precomputed weights {A=exp(k), B=k*exp(k)}.
//
//   den1 = conv(E,  A1)   num1 = conv(PE, A1) + conv(E,  B1)
//   den2 = conv(EM, A2)   num2 = conv(PEM,A2) + conv(EM, B2)
//   out  = num1/den1 + num2/den2 + bias
//
// Shapes: x[8,3,128,128], k[3,3,3,16], out[8,16,126,126] (VALID).
// Patch order in reference is (c, kh, kw); k memory layout is [kh,kw,c,f].

#define BATCH 8
#define CIN   3
#define HIN   128
#define WIN   128
#define KHW   3
#define FOUT  16
#define HOUT  126
#define WOUT  126

#define TILE  16
#define TIN   18   // TILE + 2 halo

__global__ __launch_bounds__(256, 2)
void smorph_kernel(const float* __restrict__ x,
                   const float* __restrict__ k1,
                   const float* __restrict__ k2,
                   const float* __restrict__ bias,
                   float* __restrict__ out)
{
    // Packed per-pixel maps: (e, x*e, em, -x*em) per channel.
    __shared__ float4 sMap[CIN][TIN][TIN];          // 3*18*18*16B = 15552 B
    // Packed weights per (tap j, f): (A1, B1, A2, B2).
    __shared__ float4 sW[27][FOUT];                 // 27*16*16B  =  6912 B
    __shared__ float  sBias[FOUT];

    const int tid = threadIdx.x;
    const int tx  = tid & (TILE - 1);
    const int ty  = tid >> 4;
    const int bx  = blockIdx.x, by = blockIdx.y, b = blockIdx.z;

    // ---- Weight precompute: j = c*9 + kh*3 + kw ; k mem idx = ((kh*3+kw)*3 + c)*16 + f
    if (tid < FOUT) sBias[tid] = bias[tid];
    for (int i = tid; i < 27 * FOUT; i += 256) {
        int j = i >> 4, f = i & 15;
        int c = j / 9, r = j - c * 9;               // r = kh*3+kw
        int gi = (r * 3 + c) * FOUT + f;
        float w1 = k1[gi], w2 = k2[gi];
        float a1 = __expf(w1), a2 = __expf(w2);
        sW[j][f] = make_float4(a1, w1 * a1, a2, w2 * a2);
    }

    // ---- Input tile load + map precompute (clamped at borders; clamped
    // values only feed lanes whose outputs are guarded off).
    const int gx0 = bx * TILE, gy0 = by * TILE;
    for (int i = tid; i < CIN * TIN * TIN; i += 256) {
        int c   = i / (TIN * TIN);
        int rem = i - c * (TIN * TIN);
        int r   = rem / TIN;
        int col = rem - r * TIN;
        int gy = min(gy0 + r,   HIN - 1);
        int gx = min(gx0 + col, WIN - 1);
        float v  = x[((b * CIN + c) * HIN + gy) * WIN + gx];
        float e  = __expf(v);
        float em = __expf(-v);
        sMap[c][r][col] = make_float4(e, v * e, em, -v * em);
    }
    __syncthreads();

    // ---- Accumulators: 4 per filter = 64 regs
    float num1[FOUT], den1[FOUT], num2[FOUT], den2[FOUT];
#pragma unroll
    for (int f = 0; f < FOUT; f++) {
        num1[f] = 0.f; den1[f] = 0.f; num2[f] = 0.f; den2[f] = 0.f;
    }

    // Keep the channel loop rolled to bound code size (<32KB L1.5 I$),
    // fully unroll taps x filters inside.
#pragma unroll 1
    for (int c = 0; c < CIN; c++) {
#pragma unroll
        for (int kh = 0; kh < KHW; kh++) {
#pragma unroll
            for (int kw = 0; kw < KHW; kw++) {
                const int j = c * 9 + kh * 3 + kw;
                float4 p = sMap[c][ty + kh][tx + kw];   // (e, pe, em, pem)
#pragma unroll
                for (int f = 0; f < FOUT; f++) {
                    float4 w = sW[j][f];                // (A1, B1, A2, B2)
                    den1[f] = fmaf(p.x, w.x, den1[f]);
                    num1[f] = fmaf(p.y, w.x, fmaf(p.x, w.y, num1[f]));
                    den2[f] = fmaf(p.z, w.z, den2[f]);
                    num2[f] = fmaf(p.w, w.z, fmaf(p.z, w.w, num2[f]));
                }
            }
        }
    }

    // ---- Epilogue
    const int oh = gy0 + ty, ow = gx0 + tx;
    if (oh < HOUT && ow < WOUT) {
#pragma unroll
        for (int f = 0; f < FOUT; f++) {
            float r = __fdividef(num1[f], den1[f])
                    + __fdividef(num2[f], den2[f])
                    + sBias[f];
            out[((b * FOUT + f) * HOUT + oh) * WOUT + ow] = r;
        }
    }
}

extern "C" void kernel_launch(void* const* d_in, const int* in_sizes, int n_in,
                              void* d_out, int out_size)
{
    const float* x    = (const float*)d_in[0];
    const float* k1   = (const float*)d_in[1];
    const float* k2   = (const float*)d_in[2];
    const float* bias = (const float*)d_in[3];
    float* out = (float*)d_out;

    dim3 grid((WOUT + TILE - 1) / TILE,   // 8
              (HOUT + TILE - 1) / TILE,   // 8
              BATCH);                      // 8
    smorph_kernel<<<grid, 256>>>(x, k1, k2, bias, out);
}

// round 2
// speedup vs baseline: 1.0824x; 1.0824x over previous
#include <cuda_runtime.h>
#include <cuda_bf16.h>

// SMorph layer: y = softdilate(x,k1) + softerode(x,k2) + bias
// Factorized:  exp(p+k) = exp(p)*exp(k) turns both soft-morph ops into
// four 3x3 convolutions over per-pixel maps with precomputed weights.
//
//   den1 = conv(E,  A1)   num1 = conv(PE, A1) + conv(E,  B1)
//   den2 = conv(EM, A2)   num2 = conv(PEM,A2) + conv(EM, B2)
//   out  = num1/den1 + num2/den2 + bias
//
// Round 2: dilation/erosion lanes packed into f32x2 and driven by
// fma.rn.f32x2 (Blackwell packed FFMA, PTX-only) -> 3 instr/tap/filter
// instead of 6. Layouts:
//   sMap[c][r][col] = (e, em, x*e, -x*em)   -> pairs (e,em),(pe,pem)
//   sW[j][f]        = (A1, A2, B1, B2)      -> pairs (A1,A2),(B1,B2)

#define BATCH 8
#define CIN   3
#define HIN   128
#define WIN   128
#define KHW   3
#define FOUT  16
#define HOUT  126
#define WOUT  126

#define TILE  16
#define TIN   18   // TILE + 2 halo

// packed f32x2 fma: d = a*b + d  (two fp32 lanes per instruction)
__device__ __forceinline__ void ffma2(unsigned long long& d,
                                      unsigned long long a,
                                      unsigned long long b)
{
    asm("fma.rn.f32x2 %0, %1, %2, %0;" : "+l"(d) : "l"(a), "l"(b));
}

__device__ __forceinline__ float2 unpack2(unsigned long long v)
{
    float2 r;
    asm("mov.b64 {%0, %1}, %2;" : "=f"(r.x), "=f"(r.y) : "l"(v));
    return r;
}

__global__ __launch_bounds__(256, 2)
void smorph_kernel(const float* __restrict__ x,
                   const float* __restrict__ k1,
                   const float* __restrict__ k2,
                   const float* __restrict__ bias,
                   float* __restrict__ out)
{
    __shared__ float4 sMap[CIN][TIN][TIN];          // 15552 B
    __shared__ float4 sW[27][FOUT];                 //  6912 B
    __shared__ float  sBias[FOUT];

    const int tid = threadIdx.x;
    const int tx  = tid & (TILE - 1);
    const int ty  = tid >> 4;
    const int bx  = blockIdx.x, by = blockIdx.y, b = blockIdx.z;

    // ---- Weight precompute: j = c*9 + kh*3 + kw ; k mem idx = ((kh*3+kw)*3 + c)*16 + f
    if (tid < FOUT) sBias[tid] = bias[tid];
    for (int i = tid; i < 27 * FOUT; i += 256) {
        int j = i >> 4, f = i & 15;
        int c = j / 9, r = j - c * 9;               // r = kh*3+kw
        int gi = (r * 3 + c) * FOUT + f;
        float w1 = k1[gi], w2 = k2[gi];
        float a1 = __expf(w1), a2 = __expf(w2);
        sW[j][f] = make_float4(a1, a2, w1 * a1, w2 * a2);   // (A1,A2,B1,B2)
    }

    // ---- Input tile load + map precompute (border-clamped; clamped values
    // only feed lanes whose outputs are guarded off).
    const int gx0 = bx * TILE, gy0 = by * TILE;
    for (int i = tid; i < CIN * TIN * TIN; i += 256) {
        int c   = i / (TIN * TIN);
        int rem = i - c * (TIN * TIN);
        int r   = rem / TIN;
        int col = rem - r * TIN;
        int gy = min(gy0 + r,   HIN - 1);
        int gx = min(gx0 + col, WIN - 1);
        float v  = x[((b * CIN + c) * HIN + gy) * WIN + gx];
        float e  = __expf(v);
        float em = __expf(-v);
        sMap[c][r][col] = make_float4(e, em, v * e, -v * em);  // (e,em,pe,pem)
    }
    __syncthreads();

    // ---- Packed accumulators: den[f]=(den1,den2), num[f]=(num1,num2)
    unsigned long long den[FOUT], num[FOUT];
#pragma unroll
    for (int f = 0; f < FOUT; f++) { den[f] = 0ull; num[f] = 0ull; }

#pragma unroll 1
    for (int c = 0; c < CIN; c++) {
#pragma unroll
        for (int kh = 0; kh < KHW; kh++) {
#pragma unroll
            for (int kw = 0; kw < KHW; kw++) {
                const int j = c * 9 + kh * 3 + kw;
                const ulonglong2 p =
                    *reinterpret_cast<const ulonglong2*>(&sMap[c][ty + kh][tx + kw]);
                // p.x = (e, em), p.y = (pe, pem)
#pragma unroll
                for (int f = 0; f < FOUT; f++) {
                    const ulonglong2 w =
                        *reinterpret_cast<const ulonglong2*>(&sW[j][f]);
                    // w.x = (A1, A2), w.y = (B1, B2)
                    ffma2(den[f], p.x, w.x);   // den += (e,em)*(A1,A2)
                    ffma2(num[f], p.y, w.x);   // num += (pe,pem)*(A1,A2)
                    ffma2(num[f], p.x, w.y);   // num += (e,em)*(B1,B2)
                }
            }
        }
    }

    // ---- Epilogue
    const int oh = gy0 + ty, ow = gx0 + tx;
    if (oh < HOUT && ow < WOUT) {
#pragma unroll
        for (int f = 0; f < FOUT; f++) {
            float2 n = unpack2(num[f]);
            float2 d = unpack2(den[f]);
            float r = __fdividef(n.x, d.x)
                    + __fdividef(n.y, d.y)
                    + sBias[f];
            out[((b * FOUT + f) * HOUT + oh) * WOUT + ow] = r;
        }
    }
}

extern "C" void kernel_launch(void* const* d_in, const int* in_sizes, int n_in,
                              void* d_out, int out_size)
{
    const float* x    = (const float*)d_in[0];
    const float* k1   = (const float*)d_in[1];
    const float* k2   = (const float*)d_in[2];
    const float* bias = (const float*)d_in[3];
    float* out = (float*)d_out;

    dim3 grid((WOUT + TILE - 1) / TILE,   // 8
              (HOUT + TILE - 1) / TILE,   // 8
              BATCH);                      // 8
    smorph_kernel<<<grid, 256>>>(x, k1, k2, bias, out);
}

// round 3
// speedup vs baseline: 1.1796x; 1.0898x over previous
#include <cuda_runtime.h>
#include <cuda_bf16.h>

// SMorph layer: y = softdilate(x,k1) + softerode(x,k2) + bias
// Factorized via exp(p+k)=exp(p)exp(k) into 4 accumulations over per-pixel
// maps (e, em, x*e, -x*em) with weights (A=exp(k), B=k*exp(k)):
//   den = conv((e,em),(A1,A2))   num = conv((pe,pem),(A1,A2)) + conv((e,em),(B1,B2))
//   out = num1/den1 + num2/den2 + bias       [packed f32x2 lanes: dilate|erode]
//
// Round 3: 4 pixels x 4 filters per thread.
//  - 256 threads = 4 filter-chunks x 64 pixel-groups; group g covers column
//    tx=g&15, rows ty0..ty0+3 (ty0=(g>>4)*4) of the 16x16 tile.
//  - per (c,kw): load 6 vertically-overlapping map rows ONCE, reuse across
//    the 3 kh taps of all 4 pixels -> p-LDS 27->13.5 per pixel.
//  - weights: each thread loads only its 4 filters -> w-LDS 432->108,
//    still warp-uniform (broadcast, conflict-free).

#define BATCH 8
#define CIN   3
#define HIN   128
#define WIN   128
#define FOUT  16
#define HOUT  126
#define WOUT  126

#define TILE  16
#define TIN   18   // TILE + 2 halo

__device__ __forceinline__ void ffma2(unsigned long long& d,
                                      unsigned long long a,
                                      unsigned long long b)
{
    asm("fma.rn.f32x2 %0, %1, %2, %0;" : "+l"(d) : "l"(a), "l"(b));
}

__device__ __forceinline__ float2 unpack2(unsigned long long v)
{
    float2 r;
    asm("mov.b64 {%0, %1}, %2;" : "=f"(r.x), "=f"(r.y) : "l"(v));
    return r;
}

__global__ __launch_bounds__(256, 2)
void smorph_kernel(const float* __restrict__ x,
                   const float* __restrict__ k1,
                   const float* __restrict__ k2,
                   const float* __restrict__ bias,
                   float* __restrict__ out)
{
    __shared__ float4 sMap[CIN][TIN][TIN];          // (e,em,pe,pem)  15552 B
    __shared__ float4 sW[27][FOUT];                 // (A1,A2,B1,B2)   6912 B
    __shared__ float  sBias[FOUT];

    const int tid = threadIdx.x;
    const int fc  = tid >> 6;            // filter chunk 0..3 (filters fc*4..fc*4+3)
    const int g   = tid & 63;            // pixel group
    const int tx  = g & 15;
    const int ty0 = (g >> 4) * 4;        // 4 vertically-contiguous rows
    const int bx  = blockIdx.x, by = blockIdx.y, b = blockIdx.z;

    // ---- Weight precompute: j = c*9 + kh*3 + kw ; mem idx ((kh*3+kw)*3+c)*16+f
    if (tid < FOUT) sBias[tid] = bias[tid];
    for (int i = tid; i < 27 * FOUT; i += 256) {
        int j = i >> 4, f = i & 15;
        int c = j / 9, r = j - c * 9;
        int gi = (r * 3 + c) * FOUT + f;
        float w1 = k1[gi], w2 = k2[gi];
        float a1 = __expf(w1), a2 = __expf(w2);
        sW[j][f] = make_float4(a1, a2, w1 * a1, w2 * a2);
    }

    // ---- Tile load + map precompute (border-clamped; clamped values only
    // feed guarded-off outputs).
    const int gx0 = bx * TILE, gy0 = by * TILE;
    for (int i = tid; i < CIN * TIN * TIN; i += 256) {
        int c   = i / (TIN * TIN);
        int rem = i - c * (TIN * TIN);
        int r   = rem / TIN;
        int col = rem - r * TIN;
        int gy = min(gy0 + r,   HIN - 1);
        int gx = min(gx0 + col, WIN - 1);
        float v  = x[((b * CIN + c) * HIN + gy) * WIN + gx];
        float e  = __expf(v);
        float em = __expf(-v);
        sMap[c][r][col] = make_float4(e, em, v * e, -v * em);
    }
    __syncthreads();

    // ---- Accumulators: [fi][pix], packed (dilate,erode)
    unsigned long long den[4][4], num[4][4];
#pragma unroll
    for (int fi = 0; fi < 4; fi++)
#pragma unroll
        for (int p = 0; p < 4; p++) { den[fi][p] = 0ull; num[fi][p] = 0ull; }

#pragma unroll 1
    for (int c = 0; c < CIN; c++) {
#pragma unroll
        for (int kw = 0; kw < 3; kw++) {
            // Load the 6 map rows this (c,kw) column needs, once.
            ulonglong2 p[6];
#pragma unroll
            for (int rr = 0; rr < 6; rr++)
                p[rr] = *reinterpret_cast<const ulonglong2*>(
                            &sMap[c][ty0 + rr][tx + kw]);
#pragma unroll
            for (int kh = 0; kh < 3; kh++) {
                const int j = c * 9 + kh * 3 + kw;
#pragma unroll
                for (int fi = 0; fi < 4; fi++) {
                    const ulonglong2 w =
                        *reinterpret_cast<const ulonglong2*>(&sW[j][fc * 4 + fi]);
#pragma unroll
                    for (int px = 0; px < 4; px++) {
                        ffma2(den[fi][px], p[px + kh].x, w.x); // (e,em)*(A1,A2)
                        ffma2(num[fi][px], p[px + kh].y, w.x); // (pe,pem)*(A1,A2)
                        ffma2(num[fi][px], p[px + kh].x, w.y); // (e,em)*(B1,B2)
                    }
                }
            }
        }
    }

    // ---- Epilogue: 4 filters x 4 pixels
    const int ow = gx0 + tx;
#pragma unroll
    for (int fi = 0; fi < 4; fi++) {
        const int f = fc * 4 + fi;
        const float bz = sBias[f];
#pragma unroll
        for (int px = 0; px < 4; px++) {
            const int oh = gy0 + ty0 + px;
            if (oh < HOUT && ow < WOUT) {
                float2 n = unpack2(num[fi][px]);
                float2 d = unpack2(den[fi][px]);
                out[((b * FOUT + f) * HOUT + oh) * WOUT + ow] =
                    __fdividef(n.x, d.x) + __fdividef(n.y, d.y) + bz;
            }
        }
    }
}

extern "C" void kernel_launch(void* const* d_in, const int* in_sizes, int n_in,
                              void* d_out, int out_size)
{
    const float* x    = (const float*)d_in[0];
    const float* k1   = (const float*)d_in[1];
    const float* k2   = (const float*)d_in[2];
    const float* bias = (const float*)d_in[3];
    float* out = (float*)d_out;

    dim3 grid((WOUT + TILE - 1) / TILE,   // 8
              (HOUT + TILE - 1) / TILE,   // 8
              BATCH);                      // 8
    smorph_kernel<<<grid, 256>>>(x, k1, k2, bias, out);
}